// round 2
// baseline (speedup 1.0000x reference)
#include <cuda_runtime.h>
#include <cuda_bf16.h>
#include <math.h>

// Problem constants
#define BB 4
#define SS 2048
#define HID 2048
#define HH 16
#define KVH 4
#define DD 128
#define TOK (BB*SS)            // 8192
#define NEGBIG (-1000000000.0f)
#define EPSV 1e-6f
#define SCALE 0.08838834764831845f   // 128^-0.5

// ---------------- scratch (device globals; no allocation allowed) -------------
__device__ float g_qg[(size_t)TOK * 4096];   // [tok, H*2D] q|gate interleaved per head
__device__ float g_kb[(size_t)TOK * 512];    // [tok, KV*D]
__device__ float g_vb[(size_t)TOK * 512];
__device__ float g_qh[(size_t)BB * HH * SS * DD];   // [B,H,S,D]
__device__ float g_kh[(size_t)BB * KVH * SS * DD];  // [B,KV,S,D]
__device__ float g_vh[(size_t)BB * KVH * SS * DD];
__device__ float g_attn[(size_t)TOK * 2048];        // [tok, H*D] (gated in place)

// ---------------- SGEMM: C[M,N] = A[M,K] @ B[K,N], row-major fp32 -------------
#define GBM 128
#define GBN 128
#define GBK 16

__global__ __launch_bounds__(256) void sgemm_kernel(
    const float* __restrict__ A, const float* __restrict__ Bm,
    float* __restrict__ C, int M, int N, int K)
{
    __shared__ float As[GBK][GBM];   // transposed
    __shared__ float Bs[GBK][GBN];

    const int tid = threadIdx.x;
    const int m0 = blockIdx.y * GBM;
    const int n0 = blockIdx.x * GBN;
    const int tr = tid >> 4;    // 0..15
    const int tc = tid & 15;    // 0..15

    float acc[8][8];
#pragma unroll
    for (int i = 0; i < 8; i++)
#pragma unroll
        for (int j = 0; j < 8; j++) acc[i][j] = 0.f;

    for (int k0 = 0; k0 < K; k0 += GBK) {
        // load A tile (128x16) as float4 along K, store transposed
#pragma unroll
        for (int t = 0; t < 2; t++) {
            int id = tid + t * 256;               // 0..511
            int r = id >> 2;
            int kk = (id & 3) << 2;
            float4 v = *(const float4*)(A + (size_t)(m0 + r) * K + k0 + kk);
            As[kk + 0][r] = v.x; As[kk + 1][r] = v.y;
            As[kk + 2][r] = v.z; As[kk + 3][r] = v.w;
        }
        // load B tile (16x128) float4 along N
#pragma unroll
        for (int t = 0; t < 2; t++) {
            int id = tid + t * 256;
            int kr = id >> 5;
            int c = (id & 31) << 2;
            *(float4*)(&Bs[kr][c]) = *(const float4*)(Bm + (size_t)(k0 + kr) * N + n0 + c);
        }
        __syncthreads();

#pragma unroll
        for (int kk = 0; kk < GBK; kk++) {
            float ra[8], rb[8];
            *(float4*)(ra)     = *(const float4*)(&As[kk][tr * 8]);
            *(float4*)(ra + 4) = *(const float4*)(&As[kk][tr * 8 + 4]);
            *(float4*)(rb)     = *(const float4*)(&Bs[kk][tc * 8]);
            *(float4*)(rb + 4) = *(const float4*)(&Bs[kk][tc * 8 + 4]);
#pragma unroll
            for (int i = 0; i < 8; i++)
#pragma unroll
                for (int j = 0; j < 8; j++)
                    acc[i][j] += ra[i] * rb[j];
        }
        __syncthreads();
    }

#pragma unroll
    for (int i = 0; i < 8; i++) {
        float* cp = C + (size_t)(m0 + tr * 8 + i) * N + n0 + tc * 8;
        float4 v0 = make_float4(acc[i][0], acc[i][1], acc[i][2], acc[i][3]);
        float4 v1 = make_float4(acc[i][4], acc[i][5], acc[i][6], acc[i][7]);
        *(float4*)(cp)     = v0;
        *(float4*)(cp + 4) = v1;
    }
}

// ------------- RMSNorm + RoPE for Q (16 heads/token, 1 warp/head) -------------
__global__ __launch_bounds__(512) void qnorm_rope_kernel(
    const float* __restrict__ qg, const float* __restrict__ cosb,
    const float* __restrict__ sinb, const float* __restrict__ nw,
    float* __restrict__ qh)
{
    const int t = blockIdx.x;
    const int b = t >> 11, s = t & 2047;
    const int w = threadIdx.x >> 5;         // head 0..15
    const int lane = threadIdx.x & 31;
    const int d0 = lane * 4;

    const float* p = qg + (size_t)t * 4096 + w * 256 + d0;
    float4 x = *(const float4*)p;

    float ss = x.x * x.x + x.y * x.y + x.z * x.z + x.w * x.w;
#pragma unroll
    for (int o = 16; o > 0; o >>= 1) ss += __shfl_xor_sync(0xffffffffu, ss, o);
    float inv = rsqrtf(ss * (1.f / 128.f) + EPSV);

    float nq[4];
    nq[0] = x.x * inv * (1.f + nw[d0 + 0]);
    nq[1] = x.y * inv * (1.f + nw[d0 + 1]);
    nq[2] = x.z * inv * (1.f + nw[d0 + 2]);
    nq[3] = x.w * inv * (1.f + nw[d0 + 3]);

    float up[4], dn[4];
#pragma unroll
    for (int j = 0; j < 4; j++) {
        up[j] = __shfl_sync(0xffffffffu, nq[j], (lane + 4) & 31);
        dn[j] = __shfl_sync(0xffffffffu, nq[j], (lane + 28) & 31);
    }
    float o[4];
    if (d0 < 32) {
        const float* cp = cosb + ((size_t)b * SS + s) * 32;
        const float* sp = sinb + ((size_t)b * SS + s) * 32;
#pragma unroll
        for (int j = 0; j < 4; j++) {
            int d = d0 + j;
            float cs = cp[d], sn = sp[d];
            o[j] = (d < 16) ? (nq[j] * cs - up[j] * sn)
                            : (nq[j] * cs + dn[j] * sn);
        }
    } else {
#pragma unroll
        for (int j = 0; j < 4; j++) o[j] = nq[j];
    }
    float* op = qh + (((size_t)(b * HH + w) * SS + s) * DD) + d0;
    *(float4*)op = make_float4(o[0], o[1], o[2], o[3]);
}

// ------------- RMSNorm + RoPE for K (4 heads/token) ---------------------------
__global__ __launch_bounds__(128) void knorm_rope_kernel(
    const float* __restrict__ kb, const float* __restrict__ cosb,
    const float* __restrict__ sinb, const float* __restrict__ nw,
    float* __restrict__ kh)
{
    const int t = blockIdx.x;
    const int b = t >> 11, s = t & 2047;
    const int w = threadIdx.x >> 5;         // kv head 0..3
    const int lane = threadIdx.x & 31;
    const int d0 = lane * 4;

    const float* p = kb + (size_t)t * 512 + w * 128 + d0;
    float4 x = *(const float4*)p;

    float ss = x.x * x.x + x.y * x.y + x.z * x.z + x.w * x.w;
#pragma unroll
    for (int o = 16; o > 0; o >>= 1) ss += __shfl_xor_sync(0xffffffffu, ss, o);
    float inv = rsqrtf(ss * (1.f / 128.f) + EPSV);

    float nq[4];
    nq[0] = x.x * inv * (1.f + nw[d0 + 0]);
    nq[1] = x.y * inv * (1.f + nw[d0 + 1]);
    nq[2] = x.z * inv * (1.f + nw[d0 + 2]);
    nq[3] = x.w * inv * (1.f + nw[d0 + 3]);

    float up[4], dn[4];
#pragma unroll
    for (int j = 0; j < 4; j++) {
        up[j] = __shfl_sync(0xffffffffu, nq[j], (lane + 4) & 31);
        dn[j] = __shfl_sync(0xffffffffu, nq[j], (lane + 28) & 31);
    }
    float o[4];
    if (d0 < 32) {
        const float* cp = cosb + ((size_t)b * SS + s) * 32;
        const float* sp = sinb + ((size_t)b * SS + s) * 32;
#pragma unroll
        for (int j = 0; j < 4; j++) {
            int d = d0 + j;
            float cs = cp[d], sn = sp[d];
            o[j] = (d < 16) ? (nq[j] * cs - up[j] * sn)
                            : (nq[j] * cs + dn[j] * sn);
        }
    } else {
#pragma unroll
        for (int j = 0; j < 4; j++) o[j] = nq[j];
    }
    float* op = kh + (((size_t)(b * KVH + w) * SS + s) * DD) + d0;
    *(float4*)op = make_float4(o[0], o[1], o[2], o[3]);
}

// ------------- V permute [tok, KV*D] -> [B,KV,S,D] ----------------------------
__global__ __launch_bounds__(256) void vperm_kernel(
    const float* __restrict__ vb, float* __restrict__ vh)
{
    const size_t n4 = (size_t)TOK * 512 / 4;
    for (size_t i = (size_t)blockIdx.x * blockDim.x + threadIdx.x; i < n4;
         i += (size_t)gridDim.x * blockDim.x) {
        size_t t = i >> 7;           // token
        int c4 = (int)(i & 127);
        int kv = c4 >> 5, d4 = c4 & 31;
        int b = (int)(t >> 11), s = (int)(t & 2047);
        float4 v = ((const float4*)vb)[i];
        ((float4*)vh)[(((size_t)(b * KVH + kv) * SS + s) << 5) + d4] = v;
    }
}

// ------------- Flash attention (causal, fp32, online softmax) -----------------
#define FBM 64
#define FBN 64
// smem (floats): Qt 128*64, Kt 128*64, Vs 64*128, Sb 64*68, rowC 64, rowL 64
#define SB_LD 68
#define FLASH_SMEM_FLOATS (8192*3 + 64*SB_LD + 128)
#define FLASH_SMEM_BYTES  (FLASH_SMEM_FLOATS * 4)

__global__ __launch_bounds__(256) void flash_kernel(
    const float* __restrict__ Qp, const float* __restrict__ Kp,
    const float* __restrict__ Vp, float* __restrict__ Out)
{
    extern __shared__ float sm[];
    float* Qt = sm;                       // [128][64] d-major
    float* Kt = Qt + 8192;                // [128][64] d-major
    float* Vs = Kt + 8192;                // [64][128] row-major
    float* Sb = Vs + 8192;                // [64][SB_LD]
    float* rowC = Sb + 64 * SB_LD;
    float* rowL = rowC + 64;

    const int tid = threadIdx.x;
    const int b = blockIdx.z, h = blockIdx.y;
    const int q0 = blockIdx.x * FBM;
    const int kvh = h >> 2;

    const float* qbase = Qp + ((size_t)(b * HH + h) * SS + q0) * DD;
    const float* kbase = Kp + ((size_t)(b * KVH + kvh) * SS) * DD;
    const float* vbase = Vp + ((size_t)(b * KVH + kvh) * SS) * DD;

    // load Q (transposed into smem)
    for (int idx = tid * 4; idx < FBM * DD; idx += 1024) {
        int r = idx >> 7, d = idx & 127;
        float4 v = *(const float4*)(qbase + (size_t)r * DD + d);
        Qt[(d + 0) * 64 + r] = v.x; Qt[(d + 1) * 64 + r] = v.y;
        Qt[(d + 2) * 64 + r] = v.z; Qt[(d + 3) * 64 + r] = v.w;
    }

    const int ty = tid >> 4, tx = tid & 15;    // 16x16 thread grid
    const int tr = tid >> 2, tg = tid & 3;     // softmax mapping: 4 thr/row

    float O[4][8];
#pragma unroll
    for (int i = 0; i < 4; i++)
#pragma unroll
        for (int j = 0; j < 8; j++) O[i][j] = 0.f;
    float m_run = -1e30f, l_run = 0.f;

    const int ntiles = blockIdx.x + 1;
    for (int jt = 0; jt < ntiles; jt++) {
        const int j0 = jt * FBN;
        __syncthreads();   // Q visible (iter0) / prev-iter consumers done
        // load K (transposed) and V (row-major)
        for (int idx = tid * 4; idx < FBN * DD; idx += 1024) {
            int r = idx >> 7, d = idx & 127;
            float4 kv4 = *(const float4*)(kbase + (size_t)(j0 + r) * DD + d);
            Kt[(d + 0) * 64 + r] = kv4.x; Kt[(d + 1) * 64 + r] = kv4.y;
            Kt[(d + 2) * 64 + r] = kv4.z; Kt[(d + 3) * 64 + r] = kv4.w;
            float4 vv4 = *(const float4*)(vbase + (size_t)(j0 + r) * DD + d);
            *(float4*)(&Vs[r * 128 + d]) = vv4;
        }
        __syncthreads();

        // S = Q K^T  (thread tile 4x4)
        float sacc[4][4];
#pragma unroll
        for (int i = 0; i < 4; i++)
#pragma unroll
            for (int j = 0; j < 4; j++) sacc[i][j] = 0.f;
#pragma unroll 4
        for (int d = 0; d < 128; d++) {
            float4 qv = *(const float4*)(&Qt[d * 64 + ty * 4]);
            float4 kv = *(const float4*)(&Kt[d * 64 + tx * 4]);
            float qa[4] = {qv.x, qv.y, qv.z, qv.w};
            float ka[4] = {kv.x, kv.y, kv.z, kv.w};
#pragma unroll
            for (int i = 0; i < 4; i++)
#pragma unroll
                for (int j = 0; j < 4; j++)
                    sacc[i][j] += qa[i] * ka[j];
        }
        // scale + causal mask -> Sb
#pragma unroll
        for (int i = 0; i < 4; i++)
#pragma unroll
            for (int j = 0; j < 4; j++) {
                int gr = q0 + ty * 4 + i, gc = j0 + tx * 4 + j;
                float s = sacc[i][j] * SCALE + (gc > gr ? NEGBIG : 0.f);
                Sb[(ty * 4 + i) * SB_LD + tx * 4 + j] = s;
            }
        __syncthreads();

        // online softmax (row tr, 4 threads/row)
        float mloc = -1e30f;
#pragma unroll
        for (int c = 0; c < 16; c++)
            mloc = fmaxf(mloc, Sb[tr * SB_LD + tg * 16 + c]);
        mloc = fmaxf(mloc, __shfl_xor_sync(0xffffffffu, mloc, 1));
        mloc = fmaxf(mloc, __shfl_xor_sync(0xffffffffu, mloc, 2));
        float m_new = fmaxf(m_run, mloc);
        float corr = __expf(m_run - m_new);
        float ssum = 0.f;
#pragma unroll
        for (int c = 0; c < 16; c++) {
            float p = __expf(Sb[tr * SB_LD + tg * 16 + c] - m_new);
            Sb[tr * SB_LD + tg * 16 + c] = p;
            ssum += p;
        }
        ssum += __shfl_xor_sync(0xffffffffu, ssum, 1);
        ssum += __shfl_xor_sync(0xffffffffu, ssum, 2);
        l_run = l_run * corr + ssum;
        m_run = m_new;
        if (tg == 0) rowC[tr] = corr;
        __syncthreads();

        // rescale O, accumulate P@V (thread tile: rows ty*4+i, cols tx*8+jj)
#pragma unroll
        for (int i = 0; i < 4; i++) {
            float cf = rowC[ty * 4 + i];
#pragma unroll
            for (int j = 0; j < 8; j++) O[i][j] *= cf;
        }
#pragma unroll 4
        for (int jn = 0; jn < FBN; jn++) {
            float p0 = Sb[(ty * 4 + 0) * SB_LD + jn];
            float p1 = Sb[(ty * 4 + 1) * SB_LD + jn];
            float p2 = Sb[(ty * 4 + 2) * SB_LD + jn];
            float p3 = Sb[(ty * 4 + 3) * SB_LD + jn];
            float4 v0 = *(const float4*)(&Vs[jn * 128 + tx * 8]);
            float4 v1 = *(const float4*)(&Vs[jn * 128 + tx * 8 + 4]);
            float va[8] = {v0.x, v0.y, v0.z, v0.w, v1.x, v1.y, v1.z, v1.w};
#pragma unroll
            for (int j = 0; j < 8; j++) {
                O[0][j] += p0 * va[j];
                O[1][j] += p1 * va[j];
                O[2][j] += p2 * va[j];
                O[3][j] += p3 * va[j];
            }
        }
    }

    if (tg == 0) rowL[tr] = l_run;
    __syncthreads();

    // write out: [B,S,H,D]
#pragma unroll
    for (int i = 0; i < 4; i++) {
        int gr = q0 + ty * 4 + i;
        float inv = 1.f / rowL[ty * 4 + i];
        float* op = Out + ((size_t)(b * SS + gr)) * 2048 + h * DD + tx * 8;
        *(float4*)(op)     = make_float4(O[i][0]*inv, O[i][1]*inv, O[i][2]*inv, O[i][3]*inv);
        *(float4*)(op + 4) = make_float4(O[i][4]*inv, O[i][5]*inv, O[i][6]*inv, O[i][7]*inv);
    }
}

// ------------- gating: attn *= sigmoid(gate) (in place) -----------------------
__global__ __launch_bounds__(256) void gate_kernel(
    float* __restrict__ attn, const float* __restrict__ qg)
{
    const size_t n4 = (size_t)TOK * 2048 / 4;
    for (size_t i = (size_t)blockIdx.x * blockDim.x + threadIdx.x; i < n4;
         i += (size_t)gridDim.x * blockDim.x) {
        size_t t = i >> 9;           // token (512 f4 per token)
        int c4 = (int)(i & 511);
        int hh = c4 >> 5, d4 = c4 & 31;
        const float4 g = ((const float4*)qg)[(t << 10) + hh * 64 + 32 + d4];
        float4 a = ((float4*)attn)[i];
        a.x *= 1.f / (1.f + __expf(-g.x));
        a.y *= 1.f / (1.f + __expf(-g.y));
        a.z *= 1.f / (1.f + __expf(-g.z));
        a.w *= 1.f / (1.f + __expf(-g.w));
        ((float4*)attn)[i] = a;
    }
}

// ------------------------------- launch ---------------------------------------
extern "C" void kernel_launch(void* const* d_in, const int* in_sizes, int n_in,
                              void* d_out, int out_size)
{
    (void)in_sizes; (void)n_in; (void)out_size;
    const float* X    = (const float*)d_in[0];
    const float* cosb = (const float*)d_in[1];
    const float* sinb = (const float*)d_in[2];
    // d_in[3] attention_mask: causal, reconstructed analytically
    const float* wq   = (const float*)d_in[4];
    const float* wk   = (const float*)d_in[5];
    const float* wv   = (const float*)d_in[6];
    const float* wo   = (const float*)d_in[7];
    const float* qnw  = (const float*)d_in[8];
    const float* knw  = (const float*)d_in[9];
    float* out = (float*)d_out;

    float *qg, *kb, *vb, *qh, *kh, *vh, *attn;
    cudaGetSymbolAddress((void**)&qg,   g_qg);
    cudaGetSymbolAddress((void**)&kb,   g_kb);
    cudaGetSymbolAddress((void**)&vb,   g_vb);
    cudaGetSymbolAddress((void**)&qh,   g_qh);
    cudaGetSymbolAddress((void**)&kh,   g_kh);
    cudaGetSymbolAddress((void**)&vh,   g_vh);
    cudaGetSymbolAddress((void**)&attn, g_attn);

    cudaFuncSetAttribute(flash_kernel,
        cudaFuncAttributeMaxDynamicSharedMemorySize, FLASH_SMEM_BYTES);

    // 1-3: projections
    sgemm_kernel<<<dim3(4096 / GBN, TOK / GBM), 256>>>(X, wq, qg, TOK, 4096, HID);
    sgemm_kernel<<<dim3( 512 / GBN, TOK / GBM), 256>>>(X, wk, kb, TOK,  512, HID);
    sgemm_kernel<<<dim3( 512 / GBN, TOK / GBM), 256>>>(X, wv, vb, TOK,  512, HID);

    // 4-6: norm + rope + layout
    qnorm_rope_kernel<<<TOK, 512>>>(qg, cosb, sinb, qnw, qh);
    knorm_rope_kernel<<<TOK, 128>>>(kb, cosb, sinb, knw, kh);
    vperm_kernel<<<2048, 256>>>(vb, vh);

    // 7: attention
    flash_kernel<<<dim3(SS / FBM, HH, BB), 256, FLASH_SMEM_BYTES>>>(qh, kh, vh, attn);

    // 8: gate
    gate_kernel<<<4096, 256>>>(attn, qg);

    // 9: output projection
    sgemm_kernel<<<dim3(2048 / GBN, TOK / GBM), 256>>>(attn, wo, out, TOK, 2048, HID);
}

// round 7
// speedup vs baseline: 1.6741x; 1.6741x over previous
#include <cuda_runtime.h>
#include <cuda_bf16.h>
#include <math.h>
#include <stdint.h>

// Problem constants
#define BB 4
#define SS 2048
#define HID 2048
#define HH 16
#define KVH 4
#define DD 128
#define TOK (BB*SS)            // 8192
#define NEGBIG (-1000000000.0f)
#define EPSV 1e-6f
#define SCALE 0.08838834764831845f   // 128^-0.5

// ---------------- scratch (device globals; no allocation allowed) -------------
__device__ float g_qg[(size_t)TOK * 4096];
__device__ float g_kb[(size_t)TOK * 512];
__device__ float g_vb[(size_t)TOK * 512];
__device__ float g_qh[(size_t)BB * HH * SS * DD];
__device__ float g_kh[(size_t)BB * KVH * SS * DD];
__device__ float g_vh[(size_t)BB * KVH * SS * DD];
__device__ float g_attn[(size_t)TOK * 2048];

// =================== PTX helpers ==============================================
__device__ __forceinline__ uint32_t smem_u32(const void* p) {
    uint32_t a;
    asm("{ .reg .u64 t; cvta.to.shared.u64 t, %1; cvt.u32.u64 %0, t; }" : "=r"(a) : "l"(p));
    return a;
}
__device__ __forceinline__ void cp16(uint32_t dst, const void* src) {
    asm volatile("cp.async.cg.shared.global [%0], [%1], 16;\n" :: "r"(dst), "l"(src));
}
__device__ __forceinline__ void cp_commit() {
    asm volatile("cp.async.commit_group;" ::: "memory");
}
template <int N>
__device__ __forceinline__ void cp_wait() {
    asm volatile("cp.async.wait_group %0;" :: "n"(N) : "memory");
}
__device__ __forceinline__ uint32_t f2tf32(float x) {
    uint32_t r;
    asm("cvt.rna.tf32.f32 %0, %1;" : "=r"(r) : "f"(x));
    return r;
}
__device__ __forceinline__ void mma_tf32(float* d, const uint32_t* a, const uint32_t* b) {
    asm volatile(
        "mma.sync.aligned.m16n8k8.row.col.f32.tf32.tf32.f32 "
        "{%0,%1,%2,%3}, {%4,%5,%6,%7}, {%8,%9}, {%0,%1,%2,%3};"
        : "+f"(d[0]), "+f"(d[1]), "+f"(d[2]), "+f"(d[3])
        : "r"(a[0]), "r"(a[1]), "r"(a[2]), "r"(a[3]), "r"(b[0]), "r"(b[1]));
}

// =================== tf32 mma.sync GEMM =======================================
// C[M,N] = A[M,K] @ W[K,N], both row-major fp32. 256 thr, CTA tile 128x128x32.
// 8 warps: warp_m = wid&1 (64 rows), warp_n = wid>>1 (32 cols).
// Smem swizzles (provably conflict-free for the mma fragment patterns):
//   As[r][k] at word r*32 + (k ^ ((r&7)<<2))      (128 rows x 32 k)
//   Bs[k][n] at word k*128 + (n ^ ((k&3)<<3))     (32 k x 128 n)
#define TBM 128
#define TBN 128
#define TBK 32
#define A_TILE_F (TBM * TBK)     // 4096 floats = 16KB
#define B_TILE_F (TBK * TBN)     // 4096 floats = 16KB
#define STAGE_F  (A_TILE_F + B_TILE_F)
#define GEMM_SMEM (2 * STAGE_F * 4)   // 64KB

__global__ __launch_bounds__(256, 2) void gemm_tc_kernel(
    const float* __restrict__ A, const float* __restrict__ W,
    float* __restrict__ C, int M, int N, int K)
{
    extern __shared__ float sm[];
    const uint32_t smb = smem_u32(sm);

    const int tid = threadIdx.x;
    const int wid = tid >> 5;
    const int lane = tid & 31;
    const int gr = lane >> 2;          // 0..7
    const int gc = lane & 3;           // 0..3
    const int m0 = blockIdx.y * TBM;
    const int n0 = blockIdx.x * TBN;
    const int m0w = (wid & 1) * 64;    // warp row offset
    const int n0w = (wid >> 1) * 32;   // warp col offset
    const int NCH = K / TBK;

    const uint32_t swzA = (uint32_t)gr << 2;
    const uint32_t swzB = (uint32_t)gc << 3;

    float acc[4][4][4];
#pragma unroll
    for (int i = 0; i < 4; i++)
#pragma unroll
        for (int j = 0; j < 4; j++)
#pragma unroll
            for (int r = 0; r < 4; r++) acc[i][j][r] = 0.f;

    // ---- async loader for one chunk into stage s ----
    auto load_chunk = [&](int s, int c) {
        const uint32_t aA = smb + (uint32_t)(s * STAGE_F) * 4;
        const uint32_t aB = aA + A_TILE_F * 4;
        const int kc = c * TBK;
        // A: 128 rows x 32k = 1024 x 16B
#pragma unroll
        for (int j = 0; j < 4; j++) {
            int idx = tid + j * 256;
            int row = idx >> 3, q = idx & 7;          // q: 16B chunk in row
            uint32_t w = (uint32_t)row * 32 + ((uint32_t)(q * 4) ^ (((uint32_t)row & 7) << 2));
            cp16(aA + w * 4, A + (size_t)(m0 + row) * K + kc + q * 4);
        }
        // B: 32 k-rows x 128 n = 1024 x 16B
#pragma unroll
        for (int j = 0; j < 4; j++) {
            int idx = tid + j * 256;
            int k = idx >> 5, q = idx & 31;
            uint32_t w = (uint32_t)k * 128 + ((uint32_t)(q * 4) ^ (((uint32_t)k & 3) << 3));
            cp16(aB + w * 4, W + (size_t)(kc + k) * N + n0 + q * 4);
        }
        cp_commit();
    };

    load_chunk(0, 0);
    load_chunk(1, 1);

    for (int i = 0; i < NCH; i++) {
        const int s = i & 1;
        cp_wait<1>();
        __syncthreads();

        const float* As = sm + s * STAGE_F;
        const float* Bs = As + A_TILE_F;

#pragma unroll
        for (int kk = 0; kk < TBK; kk += 8) {
            uint32_t bf[4][2];
#pragma unroll
            for (int nt = 0; nt < 4; nt++) {
                uint32_t n = (uint32_t)(n0w + nt * 8 + gr);
                bf[nt][0] = f2tf32(Bs[(uint32_t)(kk + gc) * 128 + (n ^ swzB)]);
                bf[nt][1] = f2tf32(Bs[(uint32_t)(kk + gc + 4) * 128 + (n ^ swzB)]);
            }
#pragma unroll
            for (int mt = 0; mt < 4; mt++) {
                uint32_t r0 = (uint32_t)(m0w + mt * 16 + gr);
                uint32_t ka = (uint32_t)(kk + gc) ^ swzA;
                uint32_t kb = (uint32_t)(kk + gc + 4) ^ swzA;
                uint32_t af[4];
                af[0] = f2tf32(As[r0 * 32 + ka]);
                af[1] = f2tf32(As[(r0 + 8) * 32 + ka]);
                af[2] = f2tf32(As[r0 * 32 + kb]);
                af[3] = f2tf32(As[(r0 + 8) * 32 + kb]);
#pragma unroll
                for (int nt = 0; nt < 4; nt++)
                    mma_tf32(acc[mt][nt], af, bf[nt]);
            }
        }
        __syncthreads();

        const int nxt = i + 2;
        if (nxt < NCH) load_chunk(s, nxt);
    }

    // epilogue: direct global stores (32B-sector aligned float2 per thread)
#pragma unroll
    for (int mt = 0; mt < 4; mt++) {
        int row = m0 + m0w + mt * 16 + gr;
#pragma unroll
        for (int nt = 0; nt < 4; nt++) {
            int col = n0 + n0w + nt * 8 + 2 * gc;
            float* c0 = C + (size_t)row * N + col;
            float* c1 = C + (size_t)(row + 8) * N + col;
            *(float2*)c0 = make_float2(acc[mt][nt][0], acc[mt][nt][1]);
            *(float2*)c1 = make_float2(acc[mt][nt][2], acc[mt][nt][3]);
        }
    }
}

// ------------- RMSNorm + RoPE for Q (16 heads/token, 1 warp/head) -------------
__global__ __launch_bounds__(512) void qnorm_rope_kernel(
    const float* __restrict__ qg, const float* __restrict__ cosb,
    const float* __restrict__ sinb, const float* __restrict__ nw,
    float* __restrict__ qh)
{
    const int t = blockIdx.x;
    const int b = t >> 11, s = t & 2047;
    const int w = threadIdx.x >> 5;
    const int lane = threadIdx.x & 31;
    const int d0 = lane * 4;

    const float* p = qg + (size_t)t * 4096 + w * 256 + d0;
    float4 x = *(const float4*)p;

    float ss = x.x * x.x + x.y * x.y + x.z * x.z + x.w * x.w;
#pragma unroll
    for (int o = 16; o > 0; o >>= 1) ss += __shfl_xor_sync(0xffffffffu, ss, o);
    float inv = rsqrtf(ss * (1.f / 128.f) + EPSV);

    float nq[4];
    nq[0] = x.x * inv * (1.f + nw[d0 + 0]);
    nq[1] = x.y * inv * (1.f + nw[d0 + 1]);
    nq[2] = x.z * inv * (1.f + nw[d0 + 2]);
    nq[3] = x.w * inv * (1.f + nw[d0 + 3]);

    float up[4], dn[4];
#pragma unroll
    for (int j = 0; j < 4; j++) {
        up[j] = __shfl_sync(0xffffffffu, nq[j], (lane + 4) & 31);
        dn[j] = __shfl_sync(0xffffffffu, nq[j], (lane + 28) & 31);
    }
    float o[4];
    if (d0 < 32) {
        const float* cp = cosb + ((size_t)b * SS + s) * 32;
        const float* sp = sinb + ((size_t)b * SS + s) * 32;
#pragma unroll
        for (int j = 0; j < 4; j++) {
            int d = d0 + j;
            float cs = cp[d], sn = sp[d];
            o[j] = (d < 16) ? (nq[j] * cs - up[j] * sn)
                            : (nq[j] * cs + dn[j] * sn);
        }
    } else {
#pragma unroll
        for (int j = 0; j < 4; j++) o[j] = nq[j];
    }
    float* op = qh + (((size_t)(b * HH + w) * SS + s) * DD) + d0;
    *(float4*)op = make_float4(o[0], o[1], o[2], o[3]);
}

// ------------- RMSNorm + RoPE for K (4 heads/token) ---------------------------
__global__ __launch_bounds__(128) void knorm_rope_kernel(
    const float* __restrict__ kb, const float* __restrict__ cosb,
    const float* __restrict__ sinb, const float* __restrict__ nw,
    float* __restrict__ kh)
{
    const int t = blockIdx.x;
    const int b = t >> 11, s = t & 2047;
    const int w = threadIdx.x >> 5;
    const int lane = threadIdx.x & 31;
    const int d0 = lane * 4;

    const float* p = kb + (size_t)t * 512 + w * 128 + d0;
    float4 x = *(const float4*)p;

    float ss = x.x * x.x + x.y * x.y + x.z * x.z + x.w * x.w;
#pragma unroll
    for (int o = 16; o > 0; o >>= 1) ss += __shfl_xor_sync(0xffffffffu, ss, o);
    float inv = rsqrtf(ss * (1.f / 128.f) + EPSV);

    float nq[4];
    nq[0] = x.x * inv * (1.f + nw[d0 + 0]);
    nq[1] = x.y * inv * (1.f + nw[d0 + 1]);
    nq[2] = x.z * inv * (1.f + nw[d0 + 2]);
    nq[3] = x.w * inv * (1.f + nw[d0 + 3]);

    float up[4], dn[4];
#pragma unroll
    for (int j = 0; j < 4; j++) {
        up[j] = __shfl_sync(0xffffffffu, nq[j], (lane + 4) & 31);
        dn[j] = __shfl_sync(0xffffffffu, nq[j], (lane + 28) & 31);
    }
    float o[4];
    if (d0 < 32) {
        const float* cp = cosb + ((size_t)b * SS + s) * 32;
        const float* sp = sinb + ((size_t)b * SS + s) * 32;
#pragma unroll
        for (int j = 0; j < 4; j++) {
            int d = d0 + j;
            float cs = cp[d], sn = sp[d];
            o[j] = (d < 16) ? (nq[j] * cs - up[j] * sn)
                            : (nq[j] * cs + dn[j] * sn);
        }
    } else {
#pragma unroll
        for (int j = 0; j < 4; j++) o[j] = nq[j];
    }
    float* op = kh + (((size_t)(b * KVH + w) * SS + s) * DD) + d0;
    *(float4*)op = make_float4(o[0], o[1], o[2], o[3]);
}

// ------------- V permute [tok, KV*D] -> [B,KV,S,D] ----------------------------
__global__ __launch_bounds__(256) void vperm_kernel(
    const float* __restrict__ vb, float* __restrict__ vh)
{
    const size_t n4 = (size_t)TOK * 512 / 4;
    for (size_t i = (size_t)blockIdx.x * blockDim.x + threadIdx.x; i < n4;
         i += (size_t)gridDim.x * blockDim.x) {
        size_t t = i >> 7;
        int c4 = (int)(i & 127);
        int kv = c4 >> 5, d4 = c4 & 31;
        int b = (int)(t >> 11), s = (int)(t & 2047);
        float4 v = ((const float4*)vb)[i];
        ((float4*)vh)[(((size_t)(b * KVH + kv) * SS + s) << 5) + d4] = v;
    }
}

// ------------- Flash attention (causal, fp32, online softmax) -----------------
#define FBM 64
#define FBN 64
#define SB_LD 68
#define FLASH_SMEM_FLOATS (8192*3 + 64*SB_LD + 128)
#define FLASH_SMEM_BYTES  (FLASH_SMEM_FLOATS * 4)

__global__ __launch_bounds__(256) void flash_kernel(
    const float* __restrict__ Qp, const float* __restrict__ Kp,
    const float* __restrict__ Vp, float* __restrict__ Out)
{
    extern __shared__ float smf[];
    float* Qt = smf;
    float* Kt = Qt + 8192;
    float* Vs = Kt + 8192;
    float* Sb = Vs + 8192;
    float* rowC = Sb + 64 * SB_LD;
    float* rowL = rowC + 64;

    const int tid = threadIdx.x;
    const int b = blockIdx.z, h = blockIdx.y;
    const int q0 = blockIdx.x * FBM;
    const int kvh = h >> 2;

    const float* qbase = Qp + ((size_t)(b * HH + h) * SS + q0) * DD;
    const float* kbase = Kp + ((size_t)(b * KVH + kvh) * SS) * DD;
    const float* vbase = Vp + ((size_t)(b * KVH + kvh) * SS) * DD;

    for (int idx = tid * 4; idx < FBM * DD; idx += 1024) {
        int r = idx >> 7, d = idx & 127;
        float4 v = *(const float4*)(qbase + (size_t)r * DD + d);
        Qt[(d + 0) * 64 + r] = v.x; Qt[(d + 1) * 64 + r] = v.y;
        Qt[(d + 2) * 64 + r] = v.z; Qt[(d + 3) * 64 + r] = v.w;
    }

    const int ty = tid >> 4, tx = tid & 15;
    const int tr = tid >> 2, tg = tid & 3;

    float O[4][8];
#pragma unroll
    for (int i = 0; i < 4; i++)
#pragma unroll
        for (int j = 0; j < 8; j++) O[i][j] = 0.f;
    float m_run = -1e30f, l_run = 0.f;

    const int ntiles = blockIdx.x + 1;
    for (int jt = 0; jt < ntiles; jt++) {
        const int j0 = jt * FBN;
        __syncthreads();
        for (int idx = tid * 4; idx < FBN * DD; idx += 1024) {
            int r = idx >> 7, d = idx & 127;
            float4 kv4 = *(const float4*)(kbase + (size_t)(j0 + r) * DD + d);
            Kt[(d + 0) * 64 + r] = kv4.x; Kt[(d + 1) * 64 + r] = kv4.y;
            Kt[(d + 2) * 64 + r] = kv4.z; Kt[(d + 3) * 64 + r] = kv4.w;
            float4 vv4 = *(const float4*)(vbase + (size_t)(j0 + r) * DD + d);
            *(float4*)(&Vs[r * 128 + d]) = vv4;
        }
        __syncthreads();

        float sacc[4][4];
#pragma unroll
        for (int i = 0; i < 4; i++)
#pragma unroll
            for (int j = 0; j < 4; j++) sacc[i][j] = 0.f;
#pragma unroll 4
        for (int d = 0; d < 128; d++) {
            float4 qv = *(const float4*)(&Qt[d * 64 + ty * 4]);
            float4 kv = *(const float4*)(&Kt[d * 64 + tx * 4]);
            float qa[4] = {qv.x, qv.y, qv.z, qv.w};
            float ka[4] = {kv.x, kv.y, kv.z, kv.w};
#pragma unroll
            for (int i = 0; i < 4; i++)
#pragma unroll
                for (int j = 0; j < 4; j++)
                    sacc[i][j] += qa[i] * ka[j];
        }
#pragma unroll
        for (int i = 0; i < 4; i++)
#pragma unroll
            for (int j = 0; j < 4; j++) {
                int gr = q0 + ty * 4 + i, gcn = j0 + tx * 4 + j;
                float s = sacc[i][j] * SCALE + (gcn > gr ? NEGBIG : 0.f);
                Sb[(ty * 4 + i) * SB_LD + tx * 4 + j] = s;
            }
        __syncthreads();

        float mloc = -1e30f;
#pragma unroll
        for (int c = 0; c < 16; c++)
            mloc = fmaxf(mloc, Sb[tr * SB_LD + tg * 16 + c]);
        mloc = fmaxf(mloc, __shfl_xor_sync(0xffffffffu, mloc, 1));
        mloc = fmaxf(mloc, __shfl_xor_sync(0xffffffffu, mloc, 2));
        float m_new = fmaxf(m_run, mloc);
        float corr = __expf(m_run - m_new);
        float ssum = 0.f;
#pragma unroll
        for (int c = 0; c < 16; c++) {
            float p = __expf(Sb[tr * SB_LD + tg * 16 + c] - m_new);
            Sb[tr * SB_LD + tg * 16 + c] = p;
            ssum += p;
        }
        ssum += __shfl_xor_sync(0xffffffffu, ssum, 1);
        ssum += __shfl_xor_sync(0xffffffffu, ssum, 2);
        l_run = l_run * corr + ssum;
        m_run = m_new;
        if (tg == 0) rowC[tr] = corr;
        __syncthreads();

#pragma unroll
        for (int i = 0; i < 4; i++) {
            float cf = rowC[ty * 4 + i];
#pragma unroll
            for (int j = 0; j < 8; j++) O[i][j] *= cf;
        }
#pragma unroll 4
        for (int jn = 0; jn < FBN; jn++) {
            float p0 = Sb[(ty * 4 + 0) * SB_LD + jn];
            float p1 = Sb[(ty * 4 + 1) * SB_LD + jn];
            float p2 = Sb[(ty * 4 + 2) * SB_LD + jn];
            float p3 = Sb[(ty * 4 + 3) * SB_LD + jn];
            float4 v0 = *(const float4*)(&Vs[jn * 128 + tx * 8]);
            float4 v1 = *(const float4*)(&Vs[jn * 128 + tx * 8 + 4]);
            float va[8] = {v0.x, v0.y, v0.z, v0.w, v1.x, v1.y, v1.z, v1.w};
#pragma unroll
            for (int j = 0; j < 8; j++) {
                O[0][j] += p0 * va[j];
                O[1][j] += p1 * va[j];
                O[2][j] += p2 * va[j];
                O[3][j] += p3 * va[j];
            }
        }
    }

    if (tg == 0) rowL[tr] = l_run;
    __syncthreads();

#pragma unroll
    for (int i = 0; i < 4; i++) {
        int gr = q0 + ty * 4 + i;
        float inv = 1.f / rowL[ty * 4 + i];
        float* op = Out + ((size_t)(b * SS + gr)) * 2048 + h * DD + tx * 8;
        *(float4*)(op)     = make_float4(O[i][0]*inv, O[i][1]*inv, O[i][2]*inv, O[i][3]*inv);
        *(float4*)(op + 4) = make_float4(O[i][4]*inv, O[i][5]*inv, O[i][6]*inv, O[i][7]*inv);
    }
}

// ------------- gating: attn *= sigmoid(gate) (in place) -----------------------
__global__ __launch_bounds__(256) void gate_kernel(
    float* __restrict__ attn, const float* __restrict__ qg)
{
    const size_t n4 = (size_t)TOK * 2048 / 4;
    for (size_t i = (size_t)blockIdx.x * blockDim.x + threadIdx.x; i < n4;
         i += (size_t)gridDim.x * blockDim.x) {
        size_t t = i >> 9;
        int c4 = (int)(i & 511);
        int hh = c4 >> 5, d4 = c4 & 31;
        const float4 g = ((const float4*)qg)[(t << 10) + hh * 64 + 32 + d4];
        float4 a = ((float4*)attn)[i];
        a.x *= 1.f / (1.f + __expf(-g.x));
        a.y *= 1.f / (1.f + __expf(-g.y));
        a.z *= 1.f / (1.f + __expf(-g.z));
        a.w *= 1.f / (1.f + __expf(-g.w));
        ((float4*)attn)[i] = a;
    }
}

// ------------------------------- launch ---------------------------------------
extern "C" void kernel_launch(void* const* d_in, const int* in_sizes, int n_in,
                              void* d_out, int out_size)
{
    (void)in_sizes; (void)n_in; (void)out_size;
    const float* X    = (const float*)d_in[0];
    const float* cosb = (const float*)d_in[1];
    const float* sinb = (const float*)d_in[2];
    const float* wq   = (const float*)d_in[4];
    const float* wk   = (const float*)d_in[5];
    const float* wv   = (const float*)d_in[6];
    const float* wo   = (const float*)d_in[7];
    const float* qnw  = (const float*)d_in[8];
    const float* knw  = (const float*)d_in[9];
    float* out = (float*)d_out;

    float *qg, *kb, *vb, *qh, *kh, *vh, *attn;
    cudaGetSymbolAddress((void**)&qg,   g_qg);
    cudaGetSymbolAddress((void**)&kb,   g_kb);
    cudaGetSymbolAddress((void**)&vb,   g_vb);
    cudaGetSymbolAddress((void**)&qh,   g_qh);
    cudaGetSymbolAddress((void**)&kh,   g_kh);
    cudaGetSymbolAddress((void**)&vh,   g_vh);
    cudaGetSymbolAddress((void**)&attn, g_attn);

    cudaFuncSetAttribute(flash_kernel,
        cudaFuncAttributeMaxDynamicSharedMemorySize, FLASH_SMEM_BYTES);
    cudaFuncSetAttribute(gemm_tc_kernel,
        cudaFuncAttributeMaxDynamicSharedMemorySize, GEMM_SMEM);

    // 1-3: projections on tensor cores (tf32 mma.sync)
    gemm_tc_kernel<<<dim3(4096 / TBN, TOK / TBM), 256, GEMM_SMEM>>>(X, wq, qg, TOK, 4096, HID);
    gemm_tc_kernel<<<dim3( 512 / TBN, TOK / TBM), 256, GEMM_SMEM>>>(X, wk, kb, TOK,  512, HID);
    gemm_tc_kernel<<<dim3( 512 / TBN, TOK / TBM), 256, GEMM_SMEM>>>(X, wv, vb, TOK,  512, HID);

    // 4-6: norm + rope + layout
    qnorm_rope_kernel<<<TOK, 512>>>(qg, cosb, sinb, qnw, qh);
    knorm_rope_kernel<<<TOK, 128>>>(kb, cosb, sinb, knw, kh);
    vperm_kernel<<<2048, 256>>>(vb, vh);

    // 7: attention
    flash_kernel<<<dim3(SS / FBM, HH, BB), 256, FLASH_SMEM_BYTES>>>(qh, kh, vh, attn);

    // 8: gate
    gate_kernel<<<4096, 256>>>(attn, qg);

    // 9: output projection (tf32 mma.sync)
    gemm_tc_kernel<<<dim3(2048 / TBN, TOK / TBM), 256, GEMM_SMEM>>>(attn, wo, out, TOK, 2048, HID);
}